// round 1
// baseline (speedup 1.0000x reference)
#include <cuda_runtime.h>
#include <math_constants.h>

// ---------------------------------------------------------------------------
// SC_Att_Bridge: 5-level spatial attention (CBAM-style), fp32.
// Phase 1: per-pixel channel mean+max  -> g_avg/g_max scratch
// Phase 2: dilated 7x7 conv (d=3,p=9) + bias + sigmoid -> g_att scratch
// Phase 3: out = t * (1 + att)
// ---------------------------------------------------------------------------

#define NTOT_PIX 698368   // sum over tensors of N*H*W (N=8)

__device__ float g_avg[NTOT_PIX];
__device__ float g_max[NTOT_PIX];
__device__ float g_att[NTOT_PIX];

// per-tensor tables  (shapes: (8,64,256,256)(8,128,128,128)(8,256,64,64)(8,512,32,32)(8,512,16,16))
__constant__ int c_C[5]       = {64, 128, 256, 512, 512};
__constant__ int c_HW[5]      = {65536, 16384, 4096, 1024, 256};
__constant__ int c_lgHW[5]    = {16, 14, 12, 10, 8};
__constant__ int c_W[5]       = {256, 128, 64, 32, 16};
__constant__ int c_poff[5]    = {0, 524288, 655360, 688128, 696320};      // pixel offsets
__constant__ int c_eoff[5]    = {0, 33554432, 50331648, 58720256, 62914560}; // element offsets
__constant__ int c_lgCHW[5]   = {22, 21, 20, 19, 17};
__constant__ int c_redcum[5]  = {0, 16384, 20480, 21504, 21760};  // reduce-kernel block offsets
__constant__ int c_convcum[5] = {0, 2048, 2560, 2688, 2720};      // conv-kernel block offsets
__constant__ int c_tpn[5]     = {256, 64, 16, 4, 1};              // 16x16 tiles per image
__constant__ int c_tilesX[5]  = {16, 8, 4, 2, 1};

// ---------------------------------------------------------------------------
// Phase 1: channel mean + max. Block = 256 threads = 32 pixels x 8 channel-groups.
// Lanes 0..31 of each group read 32 consecutive pixels at a fixed channel
// -> fully coalesced 128B transactions. Grid = 21824 blocks (all 5 tensors).
// ---------------------------------------------------------------------------
__global__ __launch_bounds__(256) void reduce_kernel(
    const float* __restrict__ t0, const float* __restrict__ t1,
    const float* __restrict__ t2, const float* __restrict__ t3,
    const float* __restrict__ t4)
{
    __shared__ float ss[256];
    __shared__ float sm[256];

    int b = blockIdx.x;
    int i = 0;
    if (b >= 16384) i = 1;
    if (b >= 20480) i = 2;
    if (b >= 21504) i = 3;
    if (b >= 21760) i = 4;

    const float* srcs[5] = {t0, t1, t2, t3, t4};
    const float* __restrict__ src = srcs[i];

    const int tid   = threadIdx.x;
    const int px    = tid & 31;
    const int grp   = tid >> 5;
    const int base  = (b - c_redcum[i]) << 5;
    const int pixel = base + px;                 // linear over N*H*W (exact multiple of 32)

    const int HW = c_HW[i];
    const int C  = c_C[i];
    const int n  = pixel >> c_lgHW[i];
    const int hw = pixel & (HW - 1);

    const float* __restrict__ p = src + (size_t)n * C * HW + hw;

    float s = 0.0f;
    float m = -CUDART_INF_F;
#pragma unroll 4
    for (int c = grp; c < C; c += 8) {
        float v = __ldg(p + (size_t)c * HW);
        s += v;
        m  = fmaxf(m, v);
    }
    ss[tid] = s;
    sm[tid] = m;
    __syncthreads();

    if (tid < 32) {
#pragma unroll
        for (int g = 1; g < 8; g++) {
            s += ss[g * 32 + tid];
            m  = fmaxf(m, sm[g * 32 + tid]);
        }
        int q = c_poff[i] + pixel;
        g_avg[q] = s * (1.0f / (float)C);
        g_max[q] = m;
    }
}

// ---------------------------------------------------------------------------
// Phase 2: dilated 7x7 conv (dilation 3, zero pad 9) over [avg,max], + bias,
// sigmoid. Block = 16x16 output tile; SMEM holds 34x34 halo of both maps
// (taps reach +-9). Grid = 2728 blocks (all tensors x batch x tiles).
// lax.conv is cross-correlation (no kernel flip).
// ---------------------------------------------------------------------------
__global__ __launch_bounds__(256) void conv_kernel(
    const float* __restrict__ cw, const float* __restrict__ cb)
{
    __shared__ float s_av[34 * 34];
    __shared__ float s_mx[34 * 34];
    __shared__ float s_w[98];

    int b = blockIdx.x;
    int i = 0;
    if (b >= 2048) i = 1;
    if (b >= 2560) i = 2;
    if (b >= 2688) i = 3;
    if (b >= 2720) i = 4;

    const int r      = b - c_convcum[i];
    const int tpn    = c_tpn[i];
    const int n      = r / tpn;
    const int tl     = r - n * tpn;
    const int tilesX = c_tilesX[i];
    const int ty0    = (tl / tilesX) << 4;
    const int tx0    = (tl % tilesX) << 4;
    const int Wd     = c_W[i];
    const int po     = c_poff[i] + (n << c_lgHW[i]);

    const int tid = threadIdx.x;
    if (tid < 98) s_w[tid] = cw[tid];

    // halo load: local (yy,xx) maps to global (ty0+yy-9, tx0+xx-9)
    for (int idx = tid; idx < 34 * 34; idx += 256) {
        int yy = idx / 34;
        int xx = idx - yy * 34;
        int h  = ty0 + yy - 9;
        int w  = tx0 + xx - 9;
        float a = 0.0f, m = 0.0f;
        if ((unsigned)h < (unsigned)Wd && (unsigned)w < (unsigned)Wd) { // H==W
            int q = po + h * Wd + w;
            a = g_avg[q];
            m = g_max[q];
        }
        s_av[idx] = a;
        s_mx[idx] = m;
    }
    __syncthreads();

    const int ty = tid >> 4;
    const int tx = tid & 15;

    float acc = cb[0];
#pragma unroll
    for (int kh = 0; kh < 7; kh++) {
#pragma unroll
        for (int kw = 0; kw < 7; kw++) {
            int s = (ty + kh * 3) * 34 + (tx + kw * 3);
            acc = fmaf(s_av[s], s_w[kh * 7 + kw],      acc);
            acc = fmaf(s_mx[s], s_w[49 + kh * 7 + kw], acc);
        }
    }
    float att = 1.0f / (1.0f + expf(-acc));
    g_att[po + (ty0 + ty) * Wd + (tx0 + tx)] = att;
}

// ---------------------------------------------------------------------------
// Phase 3: out = t * (1 + att). float4 everywhere. Every block of 1024
// elements lies entirely inside one tensor (all boundaries % 1024 == 0),
// so the segment branch is block-uniform. Grid = 62464 blocks exactly.
// ---------------------------------------------------------------------------
__global__ __launch_bounds__(256) void gate_kernel(
    const float* __restrict__ t0, const float* __restrict__ t1,
    const float* __restrict__ t2, const float* __restrict__ t3,
    const float* __restrict__ t4, float* __restrict__ out)
{
    const int gid = blockIdx.x * 256 + threadIdx.x;
    const int e   = gid << 2;   // element index, < 63,963,136 (fits int32)

    int i = 0;
    if (e >= 33554432) i = 1;
    if (e >= 50331648) i = 2;
    if (e >= 58720256) i = 3;
    if (e >= 62914560) i = 4;

    const float* srcs[5] = {t0, t1, t2, t3, t4};
    const float* __restrict__ src = srcs[i];

    const int local = e - c_eoff[i];
    const int n     = local >> c_lgCHW[i];
    const int hw    = local & (c_HW[i] - 1);
    const int p     = c_poff[i] + (n << c_lgHW[i]) + hw;  // %4 == 0

    const float4 a = *reinterpret_cast<const float4*>(&g_att[p]);
    const float4 v = *reinterpret_cast<const float4*>(&src[local]);

    float4 o;
    o.x = fmaf(v.x, a.x, v.x);
    o.y = fmaf(v.y, a.y, v.y);
    o.z = fmaf(v.z, a.z, v.z);
    o.w = fmaf(v.w, a.w, v.w);

    reinterpret_cast<float4*>(out)[gid] = o;
}

// ---------------------------------------------------------------------------
extern "C" void kernel_launch(void* const* d_in, const int* in_sizes, int n_in,
                              void* d_out, int out_size)
{
    const float* t0 = (const float*)d_in[0];
    const float* t1 = (const float*)d_in[1];
    const float* t2 = (const float*)d_in[2];
    const float* t3 = (const float*)d_in[3];
    const float* t4 = (const float*)d_in[4];
    const float* cw = (const float*)d_in[5];
    const float* cb = (const float*)d_in[6];
    float* out = (float*)d_out;

    reduce_kernel<<<21824, 256>>>(t0, t1, t2, t3, t4);
    conv_kernel<<<2728, 256>>>(cw, cb);
    gate_kernel<<<62464, 256>>>(t0, t1, t2, t3, t4, out);
}

// round 2
// speedup vs baseline: 1.0410x; 1.0410x over previous
#include <cuda_runtime.h>
#include <math_constants.h>

// ---------------------------------------------------------------------------
// SC_Att_Bridge: 5-level spatial attention (CBAM-style), fp32.
// Phase 1: per-pixel channel mean+max  -> g_avg/g_max scratch  (float4 lanes)
// Phase 2: dilated 7x7 conv (d=3,p=9) + bias + sigmoid -> g_att scratch
// Phase 3: out = t * (1 + att)
// ---------------------------------------------------------------------------

#define NTOT_PIX 698368   // sum over tensors of N*H*W (N=8)

__device__ float g_avg[NTOT_PIX];
__device__ float g_max[NTOT_PIX];
__device__ float g_att[NTOT_PIX];

// shapes: (8,64,256,256)(8,128,128,128)(8,256,64,64)(8,512,32,32)(8,512,16,16)
__constant__ int c_C[5]       = {64, 128, 256, 512, 512};
__constant__ int c_HW[5]      = {65536, 16384, 4096, 1024, 256};
__constant__ int c_lgHW[5]    = {16, 14, 12, 10, 8};
__constant__ int c_W[5]       = {256, 128, 64, 32, 16};
__constant__ int c_poff[5]    = {0, 524288, 655360, 688128, 696320};          // pixel offsets
__constant__ int c_eoff[5]    = {0, 33554432, 50331648, 58720256, 62914560};  // element offsets
__constant__ int c_lgCHW[5]   = {22, 21, 20, 19, 17};
__constant__ int c_redcum[5]  = {0, 4096, 5120, 5376, 5440};   // reduce blocks (128 px each)
__constant__ int c_convcum[5] = {0, 2048, 2560, 2688, 2720};   // conv blocks
__constant__ int c_tpn[5]     = {256, 64, 16, 4, 1};           // 16x16 tiles per image
__constant__ int c_tilesX[5]  = {16, 8, 4, 2, 1};

// ---------------------------------------------------------------------------
// Phase 1: channel mean + max, float4-vectorized.
// Block = 256 threads = 32 lanes x 8 channel-groups; each lane owns 4
// contiguous pixels (float4). Block covers 128 pixels. Grid = 5456.
// Loads are LDG.128, 512B per warp-instruction, fully coalesced.
// ---------------------------------------------------------------------------
__global__ __launch_bounds__(256) void reduce_kernel(
    const float* __restrict__ t0, const float* __restrict__ t1,
    const float* __restrict__ t2, const float* __restrict__ t3,
    const float* __restrict__ t4)
{
    __shared__ float4 ss[256];
    __shared__ float4 sm[256];

    int b = blockIdx.x;
    int i = 0;
    if (b >= 4096) i = 1;
    if (b >= 5120) i = 2;
    if (b >= 5376) i = 3;
    if (b >= 5440) i = 4;

    const float* srcs[5] = {t0, t1, t2, t3, t4};
    const float* __restrict__ src = srcs[i];

    const int tid   = threadIdx.x;
    const int lane  = tid & 31;
    const int grp   = tid >> 5;
    const int base  = (b - c_redcum[i]) << 7;      // 128 pixels per block
    const int pixel = base + (lane << 2);          // first of 4 contiguous pixels

    const int HW   = c_HW[i];
    const int C    = c_C[i];
    const int n    = pixel >> c_lgHW[i];
    const int hw   = pixel & (HW - 1);             // multiple of 4; no HW-crossing (HW>=256)
    const int HW4  = HW >> 2;

    const float4* __restrict__ p =
        reinterpret_cast<const float4*>(src + (size_t)n * C * HW + hw);

    float4 s = make_float4(0.f, 0.f, 0.f, 0.f);
    float4 m = make_float4(-CUDART_INF_F, -CUDART_INF_F, -CUDART_INF_F, -CUDART_INF_F);
#pragma unroll 4
    for (int c = grp; c < C; c += 8) {
        float4 v = __ldg(p + (size_t)c * HW4);
        s.x += v.x; s.y += v.y; s.z += v.z; s.w += v.w;
        m.x = fmaxf(m.x, v.x); m.y = fmaxf(m.y, v.y);
        m.z = fmaxf(m.z, v.z); m.w = fmaxf(m.w, v.w);
    }
    ss[tid] = s;
    sm[tid] = m;
    __syncthreads();

    if (tid < 32) {
#pragma unroll
        for (int g = 1; g < 8; g++) {
            float4 s2 = ss[g * 32 + tid];
            float4 m2 = sm[g * 32 + tid];
            s.x += s2.x; s.y += s2.y; s.z += s2.z; s.w += s2.w;
            m.x = fmaxf(m.x, m2.x); m.y = fmaxf(m.y, m2.y);
            m.z = fmaxf(m.z, m2.z); m.w = fmaxf(m.w, m2.w);
        }
        const float inv = 1.0f / (float)C;
        s.x *= inv; s.y *= inv; s.z *= inv; s.w *= inv;
        const int q4 = (c_poff[i] + pixel) >> 2;   // poff and pixel are %4==0
        reinterpret_cast<float4*>(g_avg)[q4] = s;
        reinterpret_cast<float4*>(g_max)[q4] = m;
    }
}

// ---------------------------------------------------------------------------
// Phase 2: dilated 7x7 conv (dilation 3, zero pad 9) over [avg,max], + bias,
// sigmoid. Block = 16x16 output tile; SMEM holds 34x34 halo of both maps.
// Grid = 2728. lax.conv is cross-correlation (no kernel flip).
// ---------------------------------------------------------------------------
__global__ __launch_bounds__(256) void conv_kernel(
    const float* __restrict__ cw, const float* __restrict__ cb)
{
    __shared__ float s_av[34 * 34];
    __shared__ float s_mx[34 * 34];
    __shared__ float s_w[98];

    int b = blockIdx.x;
    int i = 0;
    if (b >= 2048) i = 1;
    if (b >= 2560) i = 2;
    if (b >= 2688) i = 3;
    if (b >= 2720) i = 4;

    const int r      = b - c_convcum[i];
    const int tpn    = c_tpn[i];
    const int n      = r / tpn;
    const int tl     = r - n * tpn;
    const int tilesX = c_tilesX[i];
    const int ty0    = (tl / tilesX) << 4;
    const int tx0    = (tl % tilesX) << 4;
    const int Wd     = c_W[i];
    const int po     = c_poff[i] + (n << c_lgHW[i]);

    const int tid = threadIdx.x;
    if (tid < 98) s_w[tid] = cw[tid];

    for (int idx = tid; idx < 34 * 34; idx += 256) {
        int yy = idx / 34;
        int xx = idx - yy * 34;
        int h  = ty0 + yy - 9;
        int w  = tx0 + xx - 9;
        float a = 0.0f, m = 0.0f;
        if ((unsigned)h < (unsigned)Wd && (unsigned)w < (unsigned)Wd) { // H==W
            int q = po + h * Wd + w;
            a = g_avg[q];
            m = g_max[q];
        }
        s_av[idx] = a;
        s_mx[idx] = m;
    }
    __syncthreads();

    const int ty = tid >> 4;
    const int tx = tid & 15;

    float acc = cb[0];
#pragma unroll
    for (int kh = 0; kh < 7; kh++) {
#pragma unroll
        for (int kw = 0; kw < 7; kw++) {
            int s = (ty + kh * 3) * 34 + (tx + kw * 3);
            acc = fmaf(s_av[s], s_w[kh * 7 + kw],      acc);
            acc = fmaf(s_mx[s], s_w[49 + kh * 7 + kw], acc);
        }
    }
    float att = 1.0f / (1.0f + expf(-acc));
    g_att[po + (ty0 + ty) * Wd + (tx0 + tx)] = att;
}

// ---------------------------------------------------------------------------
// Phase 3: out = t * (1 + att). float4 everywhere; att is L2-resident after
// first touch (8.4MB total vs 126MB L2). Grid = 62464 blocks exactly.
// ---------------------------------------------------------------------------
__global__ __launch_bounds__(256) void gate_kernel(
    const float* __restrict__ t0, const float* __restrict__ t1,
    const float* __restrict__ t2, const float* __restrict__ t3,
    const float* __restrict__ t4, float* __restrict__ out)
{
    const int gid = blockIdx.x * 256 + threadIdx.x;
    const int e   = gid << 2;   // element index, < 63,963,136 (fits int32)

    int i = 0;
    if (e >= 33554432) i = 1;
    if (e >= 50331648) i = 2;
    if (e >= 58720256) i = 3;
    if (e >= 62914560) i = 4;

    const float* srcs[5] = {t0, t1, t2, t3, t4};
    const float* __restrict__ src = srcs[i];

    const int local = e - c_eoff[i];
    const int n     = local >> c_lgCHW[i];
    const int hw    = local & (c_HW[i] - 1);
    const int p     = c_poff[i] + (n << c_lgHW[i]) + hw;  // %4 == 0

    const float4 a = *reinterpret_cast<const float4*>(&g_att[p]);
    const float4 v = *reinterpret_cast<const float4*>(&src[local]);

    float4 o;
    o.x = fmaf(v.x, a.x, v.x);
    o.y = fmaf(v.y, a.y, v.y);
    o.z = fmaf(v.z, a.z, v.z);
    o.w = fmaf(v.w, a.w, v.w);

    reinterpret_cast<float4*>(out)[gid] = o;
}

// ---------------------------------------------------------------------------
extern "C" void kernel_launch(void* const* d_in, const int* in_sizes, int n_in,
                              void* d_out, int out_size)
{
    const float* t0 = (const float*)d_in[0];
    const float* t1 = (const float*)d_in[1];
    const float* t2 = (const float*)d_in[2];
    const float* t3 = (const float*)d_in[3];
    const float* t4 = (const float*)d_in[4];
    const float* cw = (const float*)d_in[5];
    const float* cb = (const float*)d_in[6];
    float* out = (float*)d_out;

    reduce_kernel<<<5456, 256>>>(t0, t1, t2, t3, t4);
    conv_kernel<<<2728, 256>>>(cw, cb);
    gate_kernel<<<62464, 256>>>(t0, t1, t2, t3, t4, out);
}